// round 9
// baseline (speedup 1.0000x reference)
#include <cuda_runtime.h>

// BasicRNN B=128, S=8000, H=64 — fused overlap:
//  rec blocks (bid 0..127): recurrence, 64 active threads (warps 0,1 -> SMSP 0,1),
//       publishes per-chunk progress (fence + volatile flag).
//  readout blocks (bid 128..3327): poll progress, then process a chunk of z
//       (tanh -> fc -> sigmoid -> partial sums), overlapped with the recurrence.
//       Warp workloads are SKEWED onto SMSP 2,3 (warps w%4>=2 take 14 groups,
//       w%4<2 take 6) to reduce issue contention with rec warps.
//  finish kernel: deterministic final reduce + progress-flag reset for replay.

#define BATCH 128
#define SEQ   8000
#define HID   64
#define CHUNK 1600
#define NCHUNK (SEQ / CHUNK)
#define GROUPS (SEQ / 4)        // 2000 groups of 4 timesteps
#define NCHK2 25                // readout chunks per batch
#define GCHK  (GROUPS / NCHK2)  // 80 groups per readout block

typedef unsigned long long ull;

// z scratch: [B][GROUPS][HID][4] = 262 MB
__device__ float g_z[(size_t)BATCH * GROUPS * HID * 4];
__device__ float g_pnum[BATCH * NCHK2];
__device__ float g_pden[BATCH * NCHK2];
__device__ volatile unsigned g_prog[BATCH];   // steps completed per batch

__device__ __forceinline__ ull ffma2(ull a, ull b, ull c) {
    ull d;
    asm("fma.rn.f32x2 %0, %1, %2, %3;" : "=l"(d) : "l"(a), "l"(b), "l"(c));
    return d;
}
__device__ __forceinline__ ull fadd2(ull a, ull b) {
    ull d;
    asm("add.rn.f32x2 %0, %1, %2;" : "=l"(d) : "l"(a), "l"(b));
    return d;
}
__device__ __forceinline__ float lo32(ull a) { return __int_as_float((unsigned)a); }
__device__ __forceinline__ float hi32(ull a) { return __int_as_float((unsigned)(a >> 32)); }
__device__ __forceinline__ ull pack2(float lo, float hi) {
    return (ull)__float_as_uint(lo) | ((ull)__float_as_uint(hi) << 32);
}

__device__ __forceinline__ float tanh_hw(float z) {        // MUFU.TANH
    float r;
    asm("tanh.approx.f32 %0, %1;" : "=f"(r) : "f"(z));
    return r;
}
__device__ __forceinline__ float sigmoid_tanh(float x) {   // 1 MUFU
    return fmaf(0.5f, tanh_hw(0.5f * x), 0.5f);
}

// ---------------- fused recurrence + overlapped readout ----------------
__global__ void __launch_bounds__(256, 1)
rnn_fused(const float* __restrict__ x,      // [B, S]
          const float* __restrict__ W_ih,   // [H, 1]
          const float* __restrict__ b_ih,   // [H]
          const float* __restrict__ W_hh,   // [H, H]
          const float* __restrict__ b_hh,   // [H]
          const float* __restrict__ fc_w,   // [2, H]
          const float* __restrict__ fc_b)   // [2]
{
    const int bid = blockIdx.x;
    const int tid = threadIdx.x;

    if (bid < BATCH) {
        // ================= recurrence block =================
        if (tid >= 64) return;           // 64 active threads, 2 warps
        __shared__ __align__(16) float hb[2][HID];
        __shared__ float xs[CHUNK];

        const int b = bid;
        const int r = tid;               // row 0..63

        ull w2[32];                      // full W_hh row, packed f32x2
        {
            const double* wp = (const double*)(W_hh + r * HID);
            #pragma unroll
            for (int i = 0; i < 32; i++) w2[i] = __double_as_longlong(wp[i]);
        }
        const float wih_r  = W_ih[r];
        const float bias_r = b_ih[r] + b_hh[r];

        hb[0][r] = 0.0f;   // h_0

        const float* xb = x + (long)b * SEQ;
        float4* zp = (float4*)(g_z + (size_t)b * GROUPS * HID * 4) + r;

        __syncthreads();

        for (int c = 0; c < NCHUNK; ++c) {
            for (int i = r; i < CHUNK; i += 64)
                xs[i] = xb[c * CHUNK + i];
            __syncthreads();

            #pragma unroll 1
            for (int s = 0; s < CHUNK; s += 4) {
                float xp[4];
                #pragma unroll
                for (int u = 0; u < 4; ++u)
                    xp[u] = fmaf(xs[s + u], wih_r, bias_r);

                float zq[4];
                #pragma unroll
                for (int u = 0; u < 4; ++u) {
                    const float* hsrc = hb[u & 1];
                    float*       hdst = hb[(u & 1) ^ 1];

                    const double2* h2 = (const double2*)hsrc;   // broadcast
                    ull a0 = pack2(xp[u], 0.0f);
                    ull a1 = 0ull, a2 = 0ull, a3 = 0ull;
                    #pragma unroll
                    for (int i = 0; i < 8; i++) {
                        double2 va = h2[2 * i];
                        double2 vb = h2[2 * i + 1];
                        a0 = ffma2(w2[4 * i + 0], __double_as_longlong(va.x), a0);
                        a1 = ffma2(w2[4 * i + 1], __double_as_longlong(va.y), a1);
                        a2 = ffma2(w2[4 * i + 2], __double_as_longlong(vb.x), a2);
                        a3 = ffma2(w2[4 * i + 3], __double_as_longlong(vb.y), a3);
                    }
                    ull tS = fadd2(fadd2(a0, a1), fadd2(a2, a3));
                    float z = lo32(tS) + hi32(tS);

                    zq[u]   = z;
                    hdst[r] = tanh_hw(z);
                    __syncthreads();
                }
                *zp = make_float4(zq[0], zq[1], zq[2], zq[3]);  // fire-and-forget
                zp += HID;
            }

            // publish progress (once per 1600 steps): order all threads' STGs
            __syncthreads();
            if (r == 0) {
                __threadfence();                       // gpu-scope, cumulative
                g_prog[b] = (unsigned)((c + 1) * CHUNK);
            }
        }
    } else {
        // ================= readout block =================
        __shared__ float snum[8], sden[8];

        const int bk   = bid - BATCH;            // ck-major: early blocks need early data
        const int ck   = bk / BATCH;             // seq chunk 0..24
        const int b    = bk % BATCH;             // batch
        const int w    = tid >> 5;
        const int lane = tid & 31;

        // SMSP-skewed partition: warps on SMSP 0,1 (w%4<2) take 6 groups,
        // warps on SMSP 2,3 take 14.  offsets within half-block: 0,6,12,26
        const int wm     = w & 3;
        const int gcount = (wm < 2) ? 6 : 14;
        const int goff   = (w >> 2) * 40 + ((wm == 0) ? 0 : (wm == 1) ? 6 : (wm == 2) ? 12 : 26);

        // wait until this chunk's z is published
        const unsigned need = (unsigned)((ck + 1) * GCHK * 4);
        if (tid == 0) {
            while (g_prog[b] < need) __nanosleep(1024);
        }
        __syncthreads();
        __threadfence();                         // acquire side

        const float f0a = fc_w[lane];       const float f0b = fc_w[32 + lane];
        const float f1a = fc_w[64 + lane];  const float f1b = fc_w[96 + lane];
        const float fb0 = fc_b[0];          const float fb1 = fc_b[1];

        const float4* zb = (const float4*)(g_z +
            ((size_t)b * GROUPS + (size_t)ck * GCHK + (size_t)goff) * HID * 4);

        float num = 0.0f, den = 0.0f;
        #pragma unroll 2
        for (int i = 0; i < gcount; ++i) {       // 6 or 14 groups of 4 timesteps
            const float4* zg = zb + (size_t)i * HID;
            float4 zA = zg[lane];                // rows 0..31, 4 steps
            float4 zB = zg[32 + lane];           // rows 32..63, 4 steps
            float p0[4], p1[4];
            {
                float a, bb;
                a = tanh_hw(zA.x); bb = tanh_hw(zB.x);
                p0[0] = fmaf(f0a, a, f0b * bb); p1[0] = fmaf(f1a, a, f1b * bb);
                a = tanh_hw(zA.y); bb = tanh_hw(zB.y);
                p0[1] = fmaf(f0a, a, f0b * bb); p1[1] = fmaf(f1a, a, f1b * bb);
                a = tanh_hw(zA.z); bb = tanh_hw(zB.z);
                p0[2] = fmaf(f0a, a, f0b * bb); p1[2] = fmaf(f1a, a, f1b * bb);
                a = tanh_hw(zA.w); bb = tanh_hw(zB.w);
                p0[3] = fmaf(f0a, a, f0b * bb); p1[3] = fmaf(f1a, a, f1b * bb);
            }
            #pragma unroll
            for (int o = 16; o > 0; o >>= 1) {
                #pragma unroll
                for (int j = 0; j < 4; j++) {
                    p0[j] += __shfl_xor_sync(0xffffffffu, p0[j], o);
                    p1[j] += __shfl_xor_sync(0xffffffffu, p1[j], o);
                }
            }
            #pragma unroll
            for (int j = 0; j < 4; j++) {
                float sel = sigmoid_tanh(p0[j] + fb0);
                float sc  = sigmoid_tanh(p1[j] + fb1);
                den += sel;
                num += sc * sel;
            }
        }
        if (lane == 0) { snum[w] = num; sden[w] = den; }
        __syncthreads();
        if (tid == 0) {
            float N = 0.0f, D = 0.0f;
            #pragma unroll
            for (int i = 0; i < 8; i++) { N += snum[i]; D += sden[i]; }
            g_pnum[b * NCHK2 + ck] = N;
            g_pden[b * NCHK2 + ck] = D;
        }
    }
}

// ---------------- deterministic final reduce + flag reset ----------------
__global__ void rnn_finish(float* __restrict__ out) {
    const int b = threadIdx.x;
    float N = 0.0f, D = 0.0f;
    #pragma unroll
    for (int i = 0; i < NCHK2; i++) {
        N += g_pnum[b * NCHK2 + i];
        D += g_pden[b * NCHK2 + i];
    }
    out[b] = __fdividef(N, D);
    g_prog[b] = 0u;                // reset for the next (graph-replayed) launch
}

extern "C" void kernel_launch(void* const* d_in, const int* in_sizes, int n_in,
                              void* d_out, int out_size) {
    const float* x    = (const float*)d_in[0];
    const float* W_ih = (const float*)d_in[1];
    const float* b_ih = (const float*)d_in[2];
    const float* W_hh = (const float*)d_in[3];
    const float* b_hh = (const float*)d_in[4];
    const float* fc_w = (const float*)d_in[5];
    const float* fc_b = (const float*)d_in[6];
    float* out = (float*)d_out;
    (void)in_sizes; (void)n_in; (void)out_size;

    rnn_fused<<<BATCH + BATCH * NCHK2, 256>>>(x, W_ih, b_ih, W_hh, b_hh, fc_w, fc_b);
    rnn_finish<<<1, BATCH>>>(out);
}

// round 10
// speedup vs baseline: 1.0888x; 1.0888x over previous
#include <cuda_runtime.h>

// BasicRNN B=128, S=8000, H=64 — single fused kernel:
//  rec blocks (bid 0..127): recurrence, 64 active threads; stores h=tanh(z)
//       (already computed on the critical path) to scratch; publishes
//       per-chunk progress (fence + volatile flag).
//  readout blocks (bid 128..3327): poll progress, then fc+sigmoid+partial sums
//       over a 320-step slice (no tanh needed — h is stored). Runs on the
//       ~20 SMs not holding rec blocks, fully overlapped.
//  The block finishing a batch's 25th chunk does the final reduce in-kernel
//  (atomic done-counter, fixed-order sum -> deterministic) and resets flags.

#define BATCH 128
#define SEQ   8000
#define HID   64
#define CHUNK 1600
#define NCHUNK (SEQ / CHUNK)
#define GROUPS (SEQ / 4)        // 2000 groups of 4 timesteps
#define NCHK2 25                // readout chunks per batch
#define GCHK  (GROUPS / NCHK2)  // 80 groups per readout block
#define GWARP (GCHK / 8)        // 10 groups per warp

typedef unsigned long long ull;

// h scratch: [B][GROUPS][HID][4] = 262 MB
__device__ float g_h[(size_t)BATCH * GROUPS * HID * 4];
__device__ float g_pnum[BATCH * NCHK2];
__device__ float g_pden[BATCH * NCHK2];
__device__ volatile unsigned g_prog[BATCH];   // steps completed per batch
__device__ unsigned g_done[BATCH];            // readout chunks completed

__device__ __forceinline__ ull ffma2(ull a, ull b, ull c) {
    ull d;
    asm("fma.rn.f32x2 %0, %1, %2, %3;" : "=l"(d) : "l"(a), "l"(b), "l"(c));
    return d;
}
__device__ __forceinline__ ull fadd2(ull a, ull b) {
    ull d;
    asm("add.rn.f32x2 %0, %1, %2;" : "=l"(d) : "l"(a), "l"(b));
    return d;
}
__device__ __forceinline__ float lo32(ull a) { return __int_as_float((unsigned)a); }
__device__ __forceinline__ float hi32(ull a) { return __int_as_float((unsigned)(a >> 32)); }
__device__ __forceinline__ ull pack2(float lo, float hi) {
    return (ull)__float_as_uint(lo) | ((ull)__float_as_uint(hi) << 32);
}

__device__ __forceinline__ float tanh_hw(float z) {        // MUFU.TANH
    float r;
    asm("tanh.approx.f32 %0, %1;" : "=f"(r) : "f"(z));
    return r;
}
__device__ __forceinline__ float sigmoid_tanh(float x) {   // 1 MUFU
    return fmaf(0.5f, tanh_hw(0.5f * x), 0.5f);
}

// ---------------- fused recurrence + overlapped readout + finish ----------------
__global__ void __launch_bounds__(256, 1)
rnn_fused(const float* __restrict__ x,      // [B, S]
          const float* __restrict__ W_ih,   // [H, 1]
          const float* __restrict__ b_ih,   // [H]
          const float* __restrict__ W_hh,   // [H, H]
          const float* __restrict__ b_hh,   // [H]
          const float* __restrict__ fc_w,   // [2, H]
          const float* __restrict__ fc_b,   // [2]
          float* __restrict__ out)          // [B]
{
    const int bid = blockIdx.x;
    const int tid = threadIdx.x;

    if (bid < BATCH) {
        // ================= recurrence block =================
        if (tid >= 64) return;           // 64 active threads, 2 warps
        __shared__ __align__(16) float hb[2][HID];
        __shared__ float xs[CHUNK];

        const int b = bid;
        const int r = tid;               // row 0..63

        ull w2[32];                      // full W_hh row, packed f32x2
        {
            const double* wp = (const double*)(W_hh + r * HID);
            #pragma unroll
            for (int i = 0; i < 32; i++) w2[i] = __double_as_longlong(wp[i]);
        }
        const float wih_r  = W_ih[r];
        const float bias_r = b_ih[r] + b_hh[r];

        hb[0][r] = 0.0f;   // h_0

        const float* xb = x + (long)b * SEQ;
        float4* hp = (float4*)(g_h + (size_t)b * GROUPS * HID * 4) + r;

        __syncthreads();

        for (int c = 0; c < NCHUNK; ++c) {
            for (int i = r; i < CHUNK; i += 64)
                xs[i] = xb[c * CHUNK + i];
            __syncthreads();

            #pragma unroll 1
            for (int s = 0; s < CHUNK; s += 4) {
                float xp[4];
                #pragma unroll
                for (int u = 0; u < 4; ++u)
                    xp[u] = fmaf(xs[s + u], wih_r, bias_r);

                float hq[4];
                #pragma unroll
                for (int u = 0; u < 4; ++u) {
                    const float* hsrc = hb[u & 1];
                    float*       hdst = hb[(u & 1) ^ 1];

                    const double2* h2 = (const double2*)hsrc;   // broadcast
                    ull a0 = pack2(xp[u], 0.0f);
                    ull a1 = 0ull, a2 = 0ull, a3 = 0ull;
                    #pragma unroll
                    for (int i = 0; i < 8; i++) {
                        double2 va = h2[2 * i];
                        double2 vb = h2[2 * i + 1];
                        a0 = ffma2(w2[4 * i + 0], __double_as_longlong(va.x), a0);
                        a1 = ffma2(w2[4 * i + 1], __double_as_longlong(va.y), a1);
                        a2 = ffma2(w2[4 * i + 2], __double_as_longlong(vb.x), a2);
                        a3 = ffma2(w2[4 * i + 3], __double_as_longlong(vb.y), a3);
                    }
                    ull tS = fadd2(fadd2(a0, a1), fadd2(a2, a3));
                    float z = lo32(tS) + hi32(tS);
                    float h = tanh_hw(z);

                    hq[u]   = h;         // same register feeds scratch + smem
                    hdst[r] = h;
                    __syncthreads();
                }
                *hp = make_float4(hq[0], hq[1], hq[2], hq[3]);  // fire-and-forget
                hp += HID;
            }

            // publish progress (once per 1600 steps): order all threads' STGs
            __syncthreads();
            if (r == 0) {
                __threadfence();                       // gpu-scope, cumulative
                g_prog[b] = (unsigned)((c + 1) * CHUNK);
            }
        }
    } else {
        // ================= readout block =================
        __shared__ float snum[8], sden[8];

        const int bk   = bid - BATCH;            // ck-major: early blocks need early data
        const int ck   = bk / BATCH;             // seq chunk 0..24
        const int b    = bk % BATCH;             // batch
        const int w    = tid >> 5;
        const int lane = tid & 31;

        // wait until this chunk's h is published
        const unsigned need = (unsigned)((ck + 1) * GCHK * 4);
        if (tid == 0) {
            while (g_prog[b] < need) __nanosleep(1024);
        }
        __syncthreads();
        __threadfence();                         // acquire side

        const float f0a = fc_w[lane];       const float f0b = fc_w[32 + lane];
        const float f1a = fc_w[64 + lane];  const float f1b = fc_w[96 + lane];
        const float fb0 = fc_b[0];          const float fb1 = fc_b[1];

        const float4* hbp = (const float4*)(g_h +
            ((size_t)b * GROUPS + (size_t)ck * GCHK + (size_t)w * GWARP) * HID * 4);

        float num = 0.0f, den = 0.0f;
        #pragma unroll 2
        for (int i = 0; i < GWARP; ++i) {        // 10 groups = 40 timesteps
            const float4* hg = hbp + (size_t)i * HID;
            float4 hA = hg[lane];                // rows 0..31, 4 steps (already tanh'd)
            float4 hB = hg[32 + lane];           // rows 32..63, 4 steps
            float p0[4], p1[4];
            p0[0] = fmaf(f0a, hA.x, f0b * hB.x); p1[0] = fmaf(f1a, hA.x, f1b * hB.x);
            p0[1] = fmaf(f0a, hA.y, f0b * hB.y); p1[1] = fmaf(f1a, hA.y, f1b * hB.y);
            p0[2] = fmaf(f0a, hA.z, f0b * hB.z); p1[2] = fmaf(f1a, hA.z, f1b * hB.z);
            p0[3] = fmaf(f0a, hA.w, f0b * hB.w); p1[3] = fmaf(f1a, hA.w, f1b * hB.w);
            #pragma unroll
            for (int o = 16; o > 0; o >>= 1) {
                #pragma unroll
                for (int j = 0; j < 4; j++) {
                    p0[j] += __shfl_xor_sync(0xffffffffu, p0[j], o);
                    p1[j] += __shfl_xor_sync(0xffffffffu, p1[j], o);
                }
            }
            #pragma unroll
            for (int j = 0; j < 4; j++) {
                float sel = sigmoid_tanh(p0[j] + fb0);
                float sc  = sigmoid_tanh(p1[j] + fb1);
                den += sel;
                num += sc * sel;
            }
        }
        if (lane == 0) { snum[w] = num; sden[w] = den; }
        __syncthreads();
        if (tid == 0) {
            float N = 0.0f, D = 0.0f;
            #pragma unroll
            for (int i = 0; i < 8; i++) { N += snum[i]; D += sden[i]; }
            g_pnum[b * NCHK2 + ck] = N;
            g_pden[b * NCHK2 + ck] = D;

            // completion protocol: last finisher for batch b does the reduce
            __threadfence();                                  // release partials
            unsigned d = atomicAdd(&g_done[b], 1u);
            if (d == NCHK2 - 1) {
                __threadfence();                              // acquire partials
                float NN = 0.0f, DD = 0.0f;
                #pragma unroll
                for (int i = 0; i < NCHK2; i++) {             // fixed order: deterministic
                    NN += __ldcg(&g_pnum[b * NCHK2 + i]);
                    DD += __ldcg(&g_pden[b * NCHK2 + i]);
                }
                out[b] = __fdividef(NN, DD);
                g_done[b] = 0u;                               // reset for replay
                g_prog[b] = 0u;
            }
        }
    }
}

extern "C" void kernel_launch(void* const* d_in, const int* in_sizes, int n_in,
                              void* d_out, int out_size) {
    const float* x    = (const float*)d_in[0];
    const float* W_ih = (const float*)d_in[1];
    const float* b_ih = (const float*)d_in[2];
    const float* W_hh = (const float*)d_in[3];
    const float* b_hh = (const float*)d_in[4];
    const float* fc_w = (const float*)d_in[5];
    const float* fc_b = (const float*)d_in[6];
    float* out = (float*)d_out;
    (void)in_sizes; (void)n_in; (void)out_size;

    rnn_fused<<<BATCH + BATCH * NCHK2, 256>>>(x, W_ih, b_ih, W_hh, b_hh, fc_w, fc_b, out);
}